// round 2
// baseline (speedup 1.0000x reference)
#include <cuda_runtime.h>
#include <cstdint>

// Output: (BATCH=256, SEQ=512, DIM=64) fp32.
// inputs:   (256, 512) fp32
// tables:   (3, 100000, 64) fp32
// table_ids:(512) int32, pattern [0,1,2,-1]
//
// Each thread produces 4 float4s: same (s, lane), 4 consecutive batch rows.
// -> 4 independent gather loads in flight per thread (MLP=4), one shared
//    table_id lookup/branch per thread.

#define BATCH 256
#define SEQ   512
#define DIM   64
#define VOCAB 100000
#define BGRP  4

__global__ void __launch_bounds__(256)
emb_gather_kernel(const float* __restrict__ inputs,
                  const float* __restrict__ tables,
                  const int*   __restrict__ table_ids,
                  float4*      __restrict__ out)
{
    int t = blockIdx.x * blockDim.x + threadIdx.x;  // [0, (BATCH/4)*SEQ*16)
    int lane     = t & 15;                          // float4 within 64-float row
    int row_base = t >> 4;                          // bg*SEQ + s
    int s        = row_base & (SEQ - 1);
    int bg       = row_base >> 9;                   // /SEQ

    int tid = __ldg(&table_ids[s]);

    // 4 independent input loads (stride SEQ floats apart)
    float v[BGRP];
    #pragma unroll
    for (int i = 0; i < BGRP; i++) {
        int b = bg * BGRP + i;
        v[i] = __ldg(&inputs[b * SEQ + s]);
    }

    float4 r[BGRP];
    if (tid >= 0) {
        const float4* tbase = (const float4*)tables + (long long)tid * (VOCAB * (DIM / 4));
        #pragma unroll
        for (int i = 0; i < BGRP; i++) {
            int idx = (int)v[i];                       // token id, exact in fp32
            r[i] = __ldg(tbase + idx * (DIM / 4) + lane);
        }
    } else {
        #pragma unroll
        for (int i = 0; i < BGRP; i++)
            r[i] = make_float4(v[i], v[i], v[i], v[i]);
    }

    #pragma unroll
    for (int i = 0; i < BGRP; i++) {
        int b = bg * BGRP + i;
        out[(b * SEQ + s) * (DIM / 4) + lane] = r[i];
    }
}

extern "C" void kernel_launch(void* const* d_in, const int* in_sizes, int n_in,
                              void* d_out, int out_size)
{
    const float* inputs    = (const float*)d_in[0];
    const float* tables    = (const float*)d_in[1];
    const int*   table_ids = (const int*)d_in[2];
    float4*      out       = (float4*)d_out;

    int total_threads = (BATCH / BGRP) * SEQ * (DIM / 4);  // 524288
    int threads = 256;
    int blocks  = total_threads / threads;                 // 2048
    emb_gather_kernel<<<blocks, threads>>>(inputs, tables, table_ids, out);
}

// round 4
// speedup vs baseline: 1.3295x; 1.3295x over previous
#include <cuda_runtime.h>
#include <cstdint>

// Output: (BATCH=256, SEQ=512, DIM=64) fp32.
// inputs:   (256, 512) fp32
// tables:   (3, 100000, 64) fp32
// table_ids:(512) int32, pattern [0,1,2,-1]
//
// Two-phase block: 64 rows per block.
//  Phase 1: 64 threads precompute per-row gather offsets (or numeric value)
//           into smem -> removes the dependent global->global chain.
//  Phase 2: 256 threads x 4 independent float4 gathers each (MLP=4),
//           stores are a contiguous 4KB span per step.

#define BATCH 256
#define SEQ   512
#define DIM   64
#define VOCAB 100000
#define ROWS_PER_BLK 64
#define U 4

__global__ void __launch_bounds__(256)
emb_gather_kernel(const float* __restrict__ inputs,
                  const float* __restrict__ tables,
                  const int*   __restrict__ table_ids,
                  float4*      __restrict__ out)
{
    __shared__ long long s_off[ROWS_PER_BLK];  // float4-index into tables, or -1
    __shared__ float     s_val[ROWS_PER_BLK];  // numeric value (or token, unused)

    const int tid       = threadIdx.x;
    const int row0      = blockIdx.x * ROWS_PER_BLK;      // first flattened row

    // ---- Phase 1: precompute row descriptors ----
    if (tid < ROWS_PER_BLK) {
        int row = row0 + tid;
        int s   = row & (SEQ - 1);
        float v = __ldg(&inputs[row]);
        int  tb = __ldg(&table_ids[s]);
        s_val[tid] = v;
        s_off[tid] = (tb >= 0)
                   ? ((long long)tb * VOCAB + (int)v) * (DIM / 4)
                   : -1ll;
    }
    __syncthreads();

    // ---- Phase 2: 4 independent gathers per thread ----
    long long off[U];
    float     val[U];
    #pragma unroll
    for (int k = 0; k < U; k++) {
        int j  = k * 256 + tid;        // float4 slot within block's region
        int rl = j >> 4;               // local row
        off[k] = s_off[rl];
        val[k] = s_val[rl];
    }

    const float4* t4 = (const float4*)tables;
    float4 r[U];
    #pragma unroll
    for (int k = 0; k < U; k++) {
        int lane = (k * 256 + tid) & 15;
        if (off[k] >= 0)
            r[k] = __ldg(t4 + off[k] + lane);
        else
            r[k] = make_float4(val[k], val[k], val[k], val[k]);
    }

    float4* oblk = out + (size_t)row0 * (DIM / 4);
    #pragma unroll
    for (int k = 0; k < U; k++)
        oblk[k * 256 + tid] = r[k];
}

extern "C" void kernel_launch(void* const* d_in, const int* in_sizes, int n_in,
                              void* d_out, int out_size)
{
    const float* inputs    = (const float*)d_in[0];
    const float* tables    = (const float*)d_in[1];
    const int*   table_ids = (const int*)d_in[2];
    float4*      out       = (float4*)d_out;

    int blocks = (BATCH * SEQ) / ROWS_PER_BLK;   // 2048
    emb_gather_kernel<<<blocks, 256>>>(inputs, tables, table_ids, out);
}

// round 6
// speedup vs baseline: 1.3528x; 1.0175x over previous
#include <cuda_runtime.h>
#include <cstdint>

// Output: (BATCH=256, SEQ=512, DIM=64) fp32.
// inputs:   (256, 512) fp32
// tables:   (3, 100000, 64) fp32
// table_ids:(512) int32, pattern [0,1,2,-1]
//
// 128 threads/block, 64 rows/block, U=8 float4 gathers per thread, all 8
// results held live (forced MLP=8). int32 float4-offsets. Output stored
// with .cs (evict-first) to preserve table residency in L2.

#define BATCH 256
#define SEQ   512
#define DIM   64
#define VOCAB 100000
#define ROWS_PER_BLK 64
#define THREADS 128
#define U 8

__global__ void __launch_bounds__(THREADS)
emb_gather_kernel(const float* __restrict__ inputs,
                  const float* __restrict__ tables,
                  const int*   __restrict__ table_ids,
                  float4*      __restrict__ out)
{
    __shared__ int   s_off[ROWS_PER_BLK];  // float4-index into tables, or -1
    __shared__ float s_val[ROWS_PER_BLK];  // numeric value for -1 rows

    const int tid  = threadIdx.x;
    const int row0 = blockIdx.x * ROWS_PER_BLK;

    // ---- Phase 1: per-row descriptors ----
    if (tid < ROWS_PER_BLK) {
        int row = row0 + tid;
        int s   = row & (SEQ - 1);
        float v = __ldg(&inputs[row]);
        int  tb = __ldg(&table_ids[s]);
        s_val[tid] = v;
        s_off[tid] = (tb >= 0) ? (tb * VOCAB + (int)v) * (DIM / 4) : -1;
    }
    __syncthreads();

    // ---- Phase 2: 8 independent gathers per thread ----
    int   off[U];
    float val[U];
    #pragma unroll
    for (int k = 0; k < U; k++) {
        int rl = (k * THREADS + tid) >> 4;   // local row for this f4 slot
        off[k] = s_off[rl];
        val[k] = s_val[rl];
    }

    const float4* t4 = (const float4*)tables;
    float4 r[U];
    #pragma unroll
    for (int k = 0; k < U; k++) {
        int lane = (k * THREADS + tid) & 15;
        if (off[k] >= 0)
            r[k] = __ldg(t4 + off[k] + lane);
        else
            r[k] = make_float4(val[k], val[k], val[k], val[k]);
    }

    float4* oblk = out + (size_t)row0 * (DIM / 4);
    #pragma unroll
    for (int k = 0; k < U; k++)
        __stcs(oblk + k * THREADS + tid, r[k]);
}

extern "C" void kernel_launch(void* const* d_in, const int* in_sizes, int n_in,
                              void* d_out, int out_size)
{
    const float* inputs    = (const float*)d_in[0];
    const float* tables    = (const float*)d_in[1];
    const int*   table_ids = (const int*)d_in[2];
    float4*      out       = (float4*)d_out;

    int blocks = (BATCH * SEQ) / ROWS_PER_BLK;   // 2048
    emb_gather_kernel<<<blocks, THREADS>>>(inputs, tables, table_ids, out);
}

// round 8
// speedup vs baseline: 1.3851x; 1.0239x over previous
#include <cuda_runtime.h>
#include <cstdint>

// Output: (BATCH=256, SEQ=512, DIM=64) fp32.
// inputs:   (256, 512) fp32
// tables:   (3, 100000, 64) fp32
// table_ids:(512) int32, pattern [0,1,2,-1]
//
// Forced-MLP design: one asm volatile block issues 8 LDG.128 back-to-back
// into 32 named float regs -> ptxas cannot serialize load/store pairs.
// Branchless: numeric rows gather table row 0 (L1-hit) then select.

#define BATCH 256
#define SEQ   512
#define DIM   64
#define VOCAB 100000
#define ROWS_PER_BLK 64
#define THREADS 128
#define U 8

__global__ void __launch_bounds__(THREADS)
emb_gather_kernel(const float* __restrict__ inputs,
                  const float* __restrict__ tables,
                  const int*   __restrict__ table_ids,
                  float4*      __restrict__ out)
{
    __shared__ int   s_off[ROWS_PER_BLK];  // float4-index into tables, or -1
    __shared__ float s_val[ROWS_PER_BLK];

    const int tid  = threadIdx.x;
    const int row0 = blockIdx.x * ROWS_PER_BLK;

    // ---- Phase 1: per-row descriptors ----
    if (tid < ROWS_PER_BLK) {
        int row = row0 + tid;
        int s   = row & (SEQ - 1);
        float v = __ldg(&inputs[row]);
        int  tb = __ldg(&table_ids[s]);
        s_val[tid] = v;
        s_off[tid] = (tb >= 0) ? (tb * VOCAB + (int)v) * (DIM / 4) : -1;
    }
    __syncthreads();

    int   off[U];
    float val[U];
    unsigned long long addr[U];
    #pragma unroll
    for (int k = 0; k < U; k++) {
        int j    = k * THREADS + tid;
        int rl   = j >> 4;
        int lane = j & 15;
        off[k] = s_off[rl];
        val[k] = s_val[rl];
        int safe = off[k] >= 0 ? off[k] : 0;     // numeric rows -> table row 0
        addr[k] = (unsigned long long)tables + ((unsigned long long)(unsigned)(safe + lane) << 4);
    }

    // ---- 8 LDG.128 issued back-to-back (forced MLP=8) ----
    float x[32];
    asm volatile(
        "ld.global.nc.v4.f32 {%0,%1,%2,%3},     [%32];\n\t"
        "ld.global.nc.v4.f32 {%4,%5,%6,%7},     [%33];\n\t"
        "ld.global.nc.v4.f32 {%8,%9,%10,%11},   [%34];\n\t"
        "ld.global.nc.v4.f32 {%12,%13,%14,%15}, [%35];\n\t"
        "ld.global.nc.v4.f32 {%16,%17,%18,%19}, [%36];\n\t"
        "ld.global.nc.v4.f32 {%20,%21,%22,%23}, [%37];\n\t"
        "ld.global.nc.v4.f32 {%24,%25,%26,%27}, [%38];\n\t"
        "ld.global.nc.v4.f32 {%28,%29,%30,%31}, [%39];\n\t"
        : "=f"(x[0]),  "=f"(x[1]),  "=f"(x[2]),  "=f"(x[3]),
          "=f"(x[4]),  "=f"(x[5]),  "=f"(x[6]),  "=f"(x[7]),
          "=f"(x[8]),  "=f"(x[9]),  "=f"(x[10]), "=f"(x[11]),
          "=f"(x[12]), "=f"(x[13]), "=f"(x[14]), "=f"(x[15]),
          "=f"(x[16]), "=f"(x[17]), "=f"(x[18]), "=f"(x[19]),
          "=f"(x[20]), "=f"(x[21]), "=f"(x[22]), "=f"(x[23]),
          "=f"(x[24]), "=f"(x[25]), "=f"(x[26]), "=f"(x[27]),
          "=f"(x[28]), "=f"(x[29]), "=f"(x[30]), "=f"(x[31])
        : "l"(addr[0]), "l"(addr[1]), "l"(addr[2]), "l"(addr[3]),
          "l"(addr[4]), "l"(addr[5]), "l"(addr[6]), "l"(addr[7]));

    float4* oblk = out + (size_t)row0 * (DIM / 4);
    #pragma unroll
    for (int k = 0; k < U; k++) {
        float4 r;
        if (off[k] >= 0) {
            r = make_float4(x[4*k], x[4*k+1], x[4*k+2], x[4*k+3]);
        } else {
            r = make_float4(val[k], val[k], val[k], val[k]);
        }
        __stcs(oblk + k * THREADS + tid, r);
    }
}

extern "C" void kernel_launch(void* const* d_in, const int* in_sizes, int n_in,
                              void* d_out, int out_size)
{
    const float* inputs    = (const float*)d_in[0];
    const float* tables    = (const float*)d_in[1];
    const int*   table_ids = (const int*)d_in[2];
    float4*      out       = (float4*)d_out;

    int blocks = (BATCH * SEQ) / ROWS_PER_BLK;   // 2048
    emb_gather_kernel<<<blocks, THREADS>>>(inputs, tables, table_ids, out);
}